// round 5
// baseline (speedup 1.0000x reference)
#include <cuda_runtime.h>
#include <cstdint>

// Sliding-window attention B=2 H=12 T=4096 D=64 fp32, window [q-128, q+127].
// tf32 mma.sync + per-warp band skipping + cp.async double-buffered K/V.
// CTA = 128 queries (8 warps x m16), 6 chunks of 64 keys.

constexpr int T_FIX = 4096;
constexpr int MQ    = 128;

constexpr int STRP = 68;   // P / Q stage row stride (floats)
constexpr int STRK = 68;   // K row stride
constexpr int STRV = 72;   // V row stride

constexpr int SM_P    = 0;                         // 128 x 68 floats
constexpr int KBUF_F  = 64 * STRK;                 // 4352 floats
constexpr int VBUF_F  = 64 * STRV;                 // 4608 floats
constexpr int BUF_F   = KBUF_F + VBUF_F;           // 8960 floats per stage
constexpr int SM_KV   = 128 * STRP;                // 8704
constexpr int SM_FLOATS = SM_KV + 2 * BUF_F;       // 26624
constexpr int SM_BYTES  = SM_FLOATS * 4;           // 106496

__device__ __forceinline__ float tf32r(float x) {
    float y; asm("cvt.rna.tf32.f32 %0, %1;" : "=f"(y) : "f"(x)); return y;
}
__device__ __forceinline__ float ex2(float x) {
    float y; asm("ex2.approx.ftz.f32 %0, %1;" : "=f"(y) : "f"(x)); return y;
}
__device__ __forceinline__ uint32_t smem_u32(const void* p) {
    uint32_t a;
    asm("{ .reg .u64 t; cvta.to.shared.u64 t, %1; cvt.u32.u64 %0, t; }" : "=r"(a) : "l"(p));
    return a;
}
__device__ __forceinline__ void mma8(float* c, const uint32_t* a,
                                     uint32_t b0, uint32_t b1) {
    asm volatile(
        "mma.sync.aligned.m16n8k8.row.col.f32.tf32.tf32.f32 "
        "{%0,%1,%2,%3}, {%4,%5,%6,%7}, {%8,%9}, {%0,%1,%2,%3};"
        : "+f"(c[0]), "+f"(c[1]), "+f"(c[2]), "+f"(c[3])
        : "r"(a[0]), "r"(a[1]), "r"(a[2]), "r"(a[3]), "r"(b0), "r"(b1));
}
__device__ __forceinline__ void cpa16(uint32_t dst, const void* src, uint32_t nbytes) {
    asm volatile("cp.async.ca.shared.global [%0], [%1], 16, %2;"
                 :: "r"(dst), "l"(src), "r"(nbytes) : "memory");
}
#define CPA_COMMIT() asm volatile("cp.async.commit_group;" ::: "memory")

__global__ __launch_bounds__(256, 2)
void swa_mma_kernel(const float* __restrict__ Q, const float* __restrict__ K,
                    const float* __restrict__ V, float* __restrict__ O)
{
    extern __shared__ float sm[];
    const uint32_t sb = smem_u32(sm);
    const int tid  = threadIdx.x;
    const int lane = tid & 31;
    const int w    = tid >> 5;

    const int ntiles = T_FIX / MQ;                  // 32
    const int bh = blockIdx.x / ntiles;
    const int q0 = (blockIdx.x % ntiles) * MQ;
    const size_t base = (size_t)bh * T_FIX * 64;
    const float4* Qg = (const float4*)(Q + base);
    const float4* Kg = (const float4*)(K + base);
    const float4* Vg = (const float4*)(V + base);
    float*        Ob = O + base;

    const float SC = 1.4426950408889634f * 0.125f;  // log2(e)/sqrt(64)

    // warp-uniform valid tile band (global 8-col tile index)
    const int wlo = 2 * w;
    const int whi = 2 * w + 33;

    // per-thread cp.async source/dest mapping (4 granules of 16B per tensor)
    const int g_row = tid >> 4;            // 0..15 (row block step 16)
    const int g_c4  = tid & 15;            // float4 column

    auto issue_chunk = [&](int c) {
        const int kbase = q0 - 128 + c * 64;
        const uint32_t kb = sb + (SM_KV + (c & 1) * BUF_F) * 4;
        const uint32_t vb = kb + KBUF_F * 4;
        #pragma unroll
        for (int i = 0; i < 4; i++) {
            int row = g_row + i * 16;
            int gk  = kbase + row;
            bool valid = (unsigned)gk < (unsigned)T_FIX;
            int gkc = valid ? gk : 0;
            uint32_t nb = valid ? 16u : 0u;
            cpa16(kb + (row * STRK + g_c4 * 4) * 4, Kg + (size_t)gkc * 16 + g_c4, nb);
            cpa16(vb + (row * STRV + g_c4 * 4) * 4, Vg + (size_t)gkc * 16 + g_c4, nb);
        }
        CPA_COMMIT();
    };

    // prologue: chunks 0 and 1 in flight
    issue_chunk(0);
    issue_chunk(1);

    // ---- Stage Q (scaled, tf32-rounded) into smem (overlaps cp.async) ----
    #pragma unroll
    for (int i = 0; i < 8; i++) {
        int idx = tid + i * 256;
        int row = idx >> 4, c4 = idx & 15;
        float4 v = Qg[(size_t)(q0 + row) * 16 + c4];
        v.x = tf32r(v.x * SC); v.y = tf32r(v.y * SC);
        v.z = tf32r(v.z * SC); v.w = tf32r(v.w * SC);
        *(float4*)&sm[SM_P + row * STRP + c4 * 4] = v;
    }
    __syncthreads();

    // ---- Q a-fragments, resident in registers ----
    const int rA = w * 16 + (lane >> 2);
    const int cA = lane & 3;
    uint32_t qa[8][4];
    #pragma unroll
    for (int k = 0; k < 8; k++) {
        qa[k][0] = __float_as_uint(sm[SM_P + rA * STRP + k * 8 + cA]);
        qa[k][1] = __float_as_uint(sm[SM_P + (rA + 8) * STRP + k * 8 + cA]);
        qa[k][2] = __float_as_uint(sm[SM_P + rA * STRP + k * 8 + 4 + cA]);
        qa[k][3] = __float_as_uint(sm[SM_P + (rA + 8) * STRP + k * 8 + 4 + cA]);
    }

    float o[8][4];
    #pragma unroll
    for (int n = 0; n < 8; n++)
        #pragma unroll
        for (int j = 0; j < 4; j++) o[n][j] = 0.f;
    float l0 = 0.f, l1 = 0.f;

    for (int c = 0; c < 6; c++) {
        const int kbase = q0 - 128 + c * 64;
        const int kvf   = SM_KV + (c & 1) * BUF_F;  // K buffer float offset
        const int vvf   = kvf + KBUF_F;

        if (c < 5) asm volatile("cp.async.wait_group 1;" ::: "memory");
        else       asm volatile("cp.async.wait_group 0;" ::: "memory");
        __syncthreads();

        // ---- per n-tile: S = QK^T (2 ILP chains), P = exp2*mask, stage ----
        #pragma unroll
        for (int n = 0; n < 8; n++) {
            const int gt = c * 8 + n;
            if (gt < wlo || gt > whi) continue;

            float s[4]  = {0.f, 0.f, 0.f, 0.f};
            float s2[4] = {0.f, 0.f, 0.f, 0.f};
            const float* kr = &sm[kvf + (n * 8 + (lane >> 2)) * STRK + cA];
            #pragma unroll
            for (int k = 0; k < 8; k += 2) {
                uint32_t b0 = __float_as_uint(tf32r(kr[k * 8]));
                uint32_t b1 = __float_as_uint(tf32r(kr[k * 8 + 4]));
                mma8(s, qa[k], b0, b1);
                uint32_t b2 = __float_as_uint(tf32r(kr[k * 8 + 8]));
                uint32_t b3 = __float_as_uint(tf32r(kr[k * 8 + 12]));
                mma8(s2, qa[k + 1], b2, b3);
            }
            #pragma unroll
            for (int j = 0; j < 4; j++) s[j] += s2[j];

            int cc  = c * 64 + n * 8 + 2 * cA;
            int gk0 = kbase + n * 8 + 2 * cA;
            bool in0 = ((unsigned)gk0       < (unsigned)T_FIX);
            bool in1 = ((unsigned)(gk0 + 1) < (unsigned)T_FIX);
            bool v00 = ((unsigned)(cc     - rA)       < 256u) && in0;
            bool v01 = ((unsigned)(cc + 1 - rA)       < 256u) && in1;
            bool v10 = ((unsigned)(cc     - (rA + 8)) < 256u) && in0;
            bool v11 = ((unsigned)(cc + 1 - (rA + 8)) < 256u) && in1;
            float p00 = v00 ? ex2(s[0]) : 0.f;
            float p01 = v01 ? ex2(s[1]) : 0.f;
            float p10 = v10 ? ex2(s[2]) : 0.f;
            float p11 = v11 ? ex2(s[3]) : 0.f;
            l0 += p00 + p01;
            l1 += p10 + p11;
            float2 a2 = make_float2(tf32r(p00), tf32r(p01));
            float2 b2 = make_float2(tf32r(p10), tf32r(p11));
            *(float2*)&sm[SM_P + rA * STRP + n * 8 + 2 * cA] = a2;
            *(float2*)&sm[SM_P + (rA + 8) * STRP + n * 8 + 2 * cA] = b2;
        }
        __syncwarp();

        // ---- O += P V : skip k-steps outside the band ----
        #pragma unroll
        for (int k = 0; k < 8; k++) {
            const int gt = c * 8 + k;
            if (gt < wlo || gt > whi) continue;

            uint32_t a[4];
            a[0] = __float_as_uint(sm[SM_P + rA * STRP + k * 8 + cA]);
            a[1] = __float_as_uint(sm[SM_P + (rA + 8) * STRP + k * 8 + cA]);
            a[2] = __float_as_uint(sm[SM_P + rA * STRP + k * 8 + 4 + cA]);
            a[3] = __float_as_uint(sm[SM_P + (rA + 8) * STRP + k * 8 + 4 + cA]);
            const float* vr0 = &sm[vvf + (k * 8 + cA) * STRV + (lane >> 2)];
            const float* vr1 = &sm[vvf + (k * 8 + 4 + cA) * STRV + (lane >> 2)];
            #pragma unroll
            for (int nd = 0; nd < 8; nd++) {
                uint32_t b0 = __float_as_uint(tf32r(vr0[nd * 8]));
                uint32_t b1 = __float_as_uint(tf32r(vr1[nd * 8]));
                mma8(o[nd], a, b0, b1);
            }
        }

        __syncthreads();                   // all warps done reading buffer c&1
        if (c < 4) issue_chunk(c + 2);     // refill it for chunk c+2
    }

    // ---- normalize rows and store ----
    l0 += __shfl_xor_sync(0xffffffffu, l0, 1);
    l0 += __shfl_xor_sync(0xffffffffu, l0, 2);
    l1 += __shfl_xor_sync(0xffffffffu, l1, 1);
    l1 += __shfl_xor_sync(0xffffffffu, l1, 2);
    const float inv0 = __frcp_rn(l0);
    const float inv1 = __frcp_rn(l1);

    float* orow0 = Ob + (size_t)(q0 + rA) * 64;
    float* orow1 = Ob + (size_t)(q0 + rA + 8) * 64;
    #pragma unroll
    for (int nd = 0; nd < 8; nd++) {
        float2 u0 = make_float2(o[nd][0] * inv0, o[nd][1] * inv0);
        float2 u1 = make_float2(o[nd][2] * inv1, o[nd][3] * inv1);
        *(float2*)(orow0 + nd * 8 + 2 * cA) = u0;
        *(float2*)(orow1 + nd * 8 + 2 * cA) = u1;
    }
}

extern "C" void kernel_launch(void* const* d_in, const int* in_sizes, int n_in,
                              void* d_out, int out_size) {
    const float* Q = (const float*)d_in[0];
    const float* K = (const float*)d_in[1];
    const float* V = (const float*)d_in[2];
    float*       O = (float*)d_out;

    const int BH = in_sizes[0] / (T_FIX * 64);      // 24
    static bool attr_set = false;
    if (!attr_set) {
        cudaFuncSetAttribute(swa_mma_kernel,
                             cudaFuncAttributeMaxDynamicSharedMemorySize, SM_BYTES);
        attr_set = true;
    }
    dim3 grid(BH * (T_FIX / MQ));                   // 768
    swa_mma_kernel<<<grid, 256, SM_BYTES>>>(Q, K, V, O);
}

// round 6
// speedup vs baseline: 1.0904x; 1.0904x over previous
#include <cuda_runtime.h>
#include <cstdint>

// Sliding-window attention B=2 H=12 T=4096 D=64 fp32, window [q-128, q+127].
// tf32 mma.sync + per-warp band skipping + cp.async double-buffered K/V +
// per-chunk one-touch tf32 rounding pass (no cvt in the MMA loops).
// CTA = 128 queries (8 warps x m16), 6 chunks of 64 keys.

constexpr int T_FIX = 4096;
constexpr int MQ    = 128;

constexpr int STRP = 68;   // P / Q stage row stride (floats)
constexpr int STRK = 68;   // K row stride (conflict-free QK b-frags)
constexpr int STRV = 72;   // V row stride (conflict-free PV b-frags)

constexpr int SM_P    = 0;                         // 128 x 68 floats
constexpr int KBUF_F  = 64 * STRK;                 // 4352 floats
constexpr int VBUF_F  = 64 * STRV;                 // 4608 floats
constexpr int BUF_F   = KBUF_F + VBUF_F;           // 8960 floats per stage
constexpr int SM_KV   = 128 * STRP;                // 8704
constexpr int SM_FLOATS = SM_KV + 2 * BUF_F;       // 26624
constexpr int SM_BYTES  = SM_FLOATS * 4;           // 106496

__device__ __forceinline__ float tf32r(float x) {
    float y; asm("cvt.rna.tf32.f32 %0, %1;" : "=f"(y) : "f"(x)); return y;
}
__device__ __forceinline__ float ex2(float x) {
    float y; asm("ex2.approx.ftz.f32 %0, %1;" : "=f"(y) : "f"(x)); return y;
}
__device__ __forceinline__ uint32_t smem_u32(const void* p) {
    uint32_t a;
    asm("{ .reg .u64 t; cvta.to.shared.u64 t, %1; cvt.u32.u64 %0, t; }" : "=r"(a) : "l"(p));
    return a;
}
__device__ __forceinline__ void mma8(float* c, const uint32_t* a,
                                     uint32_t b0, uint32_t b1) {
    asm volatile(
        "mma.sync.aligned.m16n8k8.row.col.f32.tf32.tf32.f32 "
        "{%0,%1,%2,%3}, {%4,%5,%6,%7}, {%8,%9}, {%0,%1,%2,%3};"
        : "+f"(c[0]), "+f"(c[1]), "+f"(c[2]), "+f"(c[3])
        : "r"(a[0]), "r"(a[1]), "r"(a[2]), "r"(a[3]), "r"(b0), "r"(b1));
}
__device__ __forceinline__ void cpa16(uint32_t dst, const void* src, uint32_t nbytes) {
    asm volatile("cp.async.ca.shared.global [%0], [%1], 16, %2;"
                 :: "r"(dst), "l"(src), "r"(nbytes) : "memory");
}
#define CPA_COMMIT() asm volatile("cp.async.commit_group;" ::: "memory")

__global__ __launch_bounds__(256, 2)
void swa_mma_kernel(const float* __restrict__ Q, const float* __restrict__ K,
                    const float* __restrict__ V, float* __restrict__ O)
{
    extern __shared__ float sm[];
    const uint32_t sb = smem_u32(sm);
    const int tid  = threadIdx.x;
    const int lane = tid & 31;
    const int w    = tid >> 5;

    const int ntiles = T_FIX / MQ;                  // 32
    const int bh = blockIdx.x / ntiles;
    const int q0 = (blockIdx.x % ntiles) * MQ;
    const size_t base = (size_t)bh * T_FIX * 64;
    const float4* Qg = (const float4*)(Q + base);
    const float4* Kg = (const float4*)(K + base);
    const float4* Vg = (const float4*)(V + base);
    float*        Ob = O + base;

    const float SC = 1.4426950408889634f * 0.125f;  // log2(e)/sqrt(64)

    // warp-uniform valid tile band (global 8-col tile index)
    const int wlo = 2 * w;
    const int whi = 2 * w + 33;

    const int g_row = tid >> 4;            // 0..15
    const int g_c4  = tid & 15;            // float4 column

    auto issue_chunk = [&](int c) {
        const int kbase = q0 - 128 + c * 64;
        const uint32_t kb = sb + (SM_KV + (c & 1) * BUF_F) * 4;
        const uint32_t vb = kb + KBUF_F * 4;
        #pragma unroll
        for (int i = 0; i < 4; i++) {
            int row = g_row + i * 16;
            int gk  = kbase + row;
            bool valid = (unsigned)gk < (unsigned)T_FIX;
            int gkc = valid ? gk : 0;
            uint32_t nb = valid ? 16u : 0u;   // nb=0 -> zero-fill dst
            cpa16(kb + (row * STRK + g_c4 * 4) * 4, Kg + (size_t)gkc * 16 + g_c4, nb);
            cpa16(vb + (row * STRV + g_c4 * 4) * 4, Vg + (size_t)gkc * 16 + g_c4, nb);
        }
        CPA_COMMIT();
    };

    // prologue: chunks 0 and 1 in flight
    issue_chunk(0);
    issue_chunk(1);

    // ---- Stage Q (scaled, tf32-rounded) into smem (overlaps cp.async) ----
    #pragma unroll
    for (int i = 0; i < 8; i++) {
        int idx = tid + i * 256;
        int row = idx >> 4, c4 = idx & 15;
        float4 v = Qg[(size_t)(q0 + row) * 16 + c4];
        v.x = tf32r(v.x * SC); v.y = tf32r(v.y * SC);
        v.z = tf32r(v.z * SC); v.w = tf32r(v.w * SC);
        *(float4*)&sm[SM_P + row * STRP + c4 * 4] = v;
    }
    __syncthreads();

    // ---- Q a-fragments, resident in registers ----
    const int rA = w * 16 + (lane >> 2);
    const int cA = lane & 3;
    uint32_t qa[8][4];
    #pragma unroll
    for (int k = 0; k < 8; k++) {
        qa[k][0] = __float_as_uint(sm[SM_P + rA * STRP + k * 8 + cA]);
        qa[k][1] = __float_as_uint(sm[SM_P + (rA + 8) * STRP + k * 8 + cA]);
        qa[k][2] = __float_as_uint(sm[SM_P + rA * STRP + k * 8 + 4 + cA]);
        qa[k][3] = __float_as_uint(sm[SM_P + (rA + 8) * STRP + k * 8 + 4 + cA]);
    }

    float o[8][4];
    #pragma unroll
    for (int n = 0; n < 8; n++)
        #pragma unroll
        for (int j = 0; j < 4; j++) o[n][j] = 0.f;
    float l0 = 0.f, l1 = 0.f;

    for (int c = 0; c < 6; c++) {
        const int kbase = q0 - 128 + c * 64;
        const int kvf   = SM_KV + (c & 1) * BUF_F;  // K buffer float offset
        const int vvf   = kvf + KBUF_F;

        if (c < 5) asm volatile("cp.async.wait_group 1;" ::: "memory");
        else       asm volatile("cp.async.wait_group 0;" ::: "memory");
        __syncthreads();

        // ---- one-touch tf32 rounding pass over the whole stage (K+V) ----
        {
            float4* b4 = (float4*)&sm[kvf];         // K then V, contiguous
            #pragma unroll 3
            for (int i = tid; i < BUF_F / 4; i += 256) {
                float4 v = b4[i];
                v.x = tf32r(v.x); v.y = tf32r(v.y);
                v.z = tf32r(v.z); v.w = tf32r(v.w);
                b4[i] = v;
            }
        }
        __syncthreads();

        // ---- per n-tile: S = QK^T (2 ILP chains), P = exp2*mask, stage ----
        #pragma unroll
        for (int n = 0; n < 8; n++) {
            const int gt = c * 8 + n;
            if (gt < wlo || gt > whi) continue;     // warp-uniform skip

            float s[4]  = {0.f, 0.f, 0.f, 0.f};
            float s2[4] = {0.f, 0.f, 0.f, 0.f};
            const float* kr = &sm[kvf + (n * 8 + (lane >> 2)) * STRK + cA];
            #pragma unroll
            for (int k = 0; k < 8; k += 2) {
                uint32_t b0 = __float_as_uint(kr[k * 8]);
                uint32_t b1 = __float_as_uint(kr[k * 8 + 4]);
                mma8(s, qa[k], b0, b1);
                uint32_t b2 = __float_as_uint(kr[k * 8 + 8]);
                uint32_t b3 = __float_as_uint(kr[k * 8 + 12]);
                mma8(s2, qa[k + 1], b2, b3);
            }
            #pragma unroll
            for (int j = 0; j < 4; j++) s[j] += s2[j];

            int cc  = c * 64 + n * 8 + 2 * cA;
            int gk0 = kbase + n * 8 + 2 * cA;
            bool in0 = ((unsigned)gk0       < (unsigned)T_FIX);
            bool in1 = ((unsigned)(gk0 + 1) < (unsigned)T_FIX);
            bool v00 = ((unsigned)(cc     - rA)       < 256u) && in0;
            bool v01 = ((unsigned)(cc + 1 - rA)       < 256u) && in1;
            bool v10 = ((unsigned)(cc     - (rA + 8)) < 256u) && in0;
            bool v11 = ((unsigned)(cc + 1 - (rA + 8)) < 256u) && in1;
            float p00 = v00 ? ex2(s[0]) : 0.f;
            float p01 = v01 ? ex2(s[1]) : 0.f;
            float p10 = v10 ? ex2(s[2]) : 0.f;
            float p11 = v11 ? ex2(s[3]) : 0.f;
            l0 += p00 + p01;
            l1 += p10 + p11;
            float2 a2 = make_float2(tf32r(p00), tf32r(p01));
            float2 b2 = make_float2(tf32r(p10), tf32r(p11));
            *(float2*)&sm[SM_P + rA * STRP + n * 8 + 2 * cA] = a2;
            *(float2*)&sm[SM_P + (rA + 8) * STRP + n * 8 + 2 * cA] = b2;
        }
        __syncwarp();   // P rows are warp-private

        // ---- O += P V : skip k-steps outside the band ----
        #pragma unroll
        for (int k = 0; k < 8; k++) {
            const int gt = c * 8 + k;
            if (gt < wlo || gt > whi) continue;

            uint32_t a[4];
            a[0] = __float_as_uint(sm[SM_P + rA * STRP + k * 8 + cA]);
            a[1] = __float_as_uint(sm[SM_P + (rA + 8) * STRP + k * 8 + cA]);
            a[2] = __float_as_uint(sm[SM_P + rA * STRP + k * 8 + 4 + cA]);
            a[3] = __float_as_uint(sm[SM_P + (rA + 8) * STRP + k * 8 + 4 + cA]);
            const float* vr0 = &sm[vvf + (k * 8 + cA) * STRV + (lane >> 2)];
            const float* vr1 = &sm[vvf + (k * 8 + 4 + cA) * STRV + (lane >> 2)];
            #pragma unroll
            for (int nd = 0; nd < 8; nd++) {
                uint32_t b0 = __float_as_uint(vr0[nd * 8]);
                uint32_t b1 = __float_as_uint(vr1[nd * 8]);
                mma8(o[nd], a, b0, b1);
            }
        }

        __syncthreads();                   // buffer c&1 fully consumed
        if (c < 4) issue_chunk(c + 2);     // refill it for chunk c+2
    }

    // ---- normalize rows and store ----
    l0 += __shfl_xor_sync(0xffffffffu, l0, 1);
    l0 += __shfl_xor_sync(0xffffffffu, l0, 2);
    l1 += __shfl_xor_sync(0xffffffffu, l1, 1);
    l1 += __shfl_xor_sync(0xffffffffu, l1, 2);
    const float inv0 = __frcp_rn(l0);
    const float inv1 = __frcp_rn(l1);

    float* orow0 = Ob + (size_t)(q0 + rA) * 64;
    float* orow1 = Ob + (size_t)(q0 + rA + 8) * 64;
    #pragma unroll
    for (int nd = 0; nd < 8; nd++) {
        float2 u0 = make_float2(o[nd][0] * inv0, o[nd][1] * inv0);
        float2 u1 = make_float2(o[nd][2] * inv1, o[nd][3] * inv1);
        *(float2*)(orow0 + nd * 8 + 2 * cA) = u0;
        *(float2*)(orow1 + nd * 8 + 2 * cA) = u1;
    }
}

extern "C" void kernel_launch(void* const* d_in, const int* in_sizes, int n_in,
                              void* d_out, int out_size) {
    const float* Q = (const float*)d_in[0];
    const float* K = (const float*)d_in[1];
    const float* V = (const float*)d_in[2];
    float*       O = (float*)d_out;

    const int BH = in_sizes[0] / (T_FIX * 64);      // 24
    static bool attr_set = false;
    if (!attr_set) {
        cudaFuncSetAttribute(swa_mma_kernel,
                             cudaFuncAttributeMaxDynamicSharedMemorySize, SM_BYTES);
        attr_set = true;
    }
    dim3 grid(BH * (T_FIX / MQ));                   // 768
    swa_mma_kernel<<<grid, 256, SM_BYTES>>>(Q, K, V, O);
}

// round 7
// speedup vs baseline: 1.0912x; 1.0007x over previous
#include <cuda_runtime.h>
#include <cstdint>

// Sliding-window attention B=2 H=12 T=4096 D=64 fp32, window [q-128, q+127].
// tf32 mma.sync, CTA = 128 queries (8 warps x m16), 6 chunks of 64 keys.
// Round 7: fused per-tile QK->softmax->PV with shuffle-based C->A fragment
// transpose (no P smem round trip), register-prefetched double-buffered K/V
// fill with a single barrier per chunk.

constexpr int T_FIX = 4096;
constexpr int MQ    = 128;

constexpr int STRK = 68;   // K row stride (conflict-free QK b-frags)
constexpr int STRV = 72;   // V row stride (conflict-free PV b-frags)
constexpr int STRQ = 68;   // Q staging stride

constexpr int KBUF_F = 64 * STRK;              // 4352 floats
constexpr int BUF_F  = KBUF_F + 64 * STRV;     // 8960 floats per stage
constexpr int SM_BYTES = 2 * BUF_F * 4;        // 71680 B  (Q stage aliases buf1)

__device__ __forceinline__ float tf32r(float x) {
    float y; asm("cvt.rna.tf32.f32 %0, %1;" : "=f"(y) : "f"(x)); return y;
}
__device__ __forceinline__ float ex2(float x) {
    float y; asm("ex2.approx.ftz.f32 %0, %1;" : "=f"(y) : "f"(x)); return y;
}
__device__ __forceinline__ void mma8(float* c, const uint32_t* a,
                                     uint32_t b0, uint32_t b1) {
    asm volatile(
        "mma.sync.aligned.m16n8k8.row.col.f32.tf32.tf32.f32 "
        "{%0,%1,%2,%3}, {%4,%5,%6,%7}, {%8,%9}, {%0,%1,%2,%3};"
        : "+f"(c[0]), "+f"(c[1]), "+f"(c[2]), "+f"(c[3])
        : "r"(a[0]), "r"(a[1]), "r"(a[2]), "r"(a[3]), "r"(b0), "r"(b1));
}

__global__ __launch_bounds__(256, 2)
void swa_mma_kernel(const float* __restrict__ Q, const float* __restrict__ K,
                    const float* __restrict__ V, float* __restrict__ O)
{
    extern __shared__ float sm[];
    const int tid  = threadIdx.x;
    const int lane = tid & 31;
    const int w    = tid >> 5;

    const int ntiles = T_FIX / MQ;                  // 32
    const int bh = blockIdx.x / ntiles;
    const int q0 = (blockIdx.x % ntiles) * MQ;
    const size_t base = (size_t)bh * T_FIX * 64;
    const float4* Qg = (const float4*)(Q + base);
    const float4* Kg = (const float4*)(K + base);
    const float4* Vg = (const float4*)(V + base);
    float*        Ob = O + base;

    const float SC = 1.4426950408889634f * 0.125f;  // log2(e)/sqrt(64)

    // warp-uniform valid tile band (global 8-col tile index)
    const int wlo = 2 * w;
    const int whi = 2 * w + 33;

    const int g_row = tid >> 4;            // 0..15
    const int g_c4  = tid & 15;            // float4 column

    // ---- Stage Q (scaled, tf32-rounded) into buf1 region ----
    #pragma unroll
    for (int i = 0; i < 8; i++) {
        int idx = tid + i * 256;
        int row = idx >> 4, c4 = idx & 15;
        float4 v = Qg[(size_t)(q0 + row) * 16 + c4];
        v.x = tf32r(v.x * SC); v.y = tf32r(v.y * SC);
        v.z = tf32r(v.z * SC); v.w = tf32r(v.w * SC);
        *(float4*)&sm[BUF_F + row * STRQ + c4 * 4] = v;
    }
    __syncthreads();

    // ---- Q a-fragments, resident in registers ----
    const int rA = w * 16 + (lane >> 2);
    const int cA = lane & 3;
    uint32_t qa[8][4];
    #pragma unroll
    for (int k = 0; k < 8; k++) {
        qa[k][0] = __float_as_uint(sm[BUF_F + rA * STRQ + k * 8 + cA]);
        qa[k][1] = __float_as_uint(sm[BUF_F + (rA + 8) * STRQ + k * 8 + cA]);
        qa[k][2] = __float_as_uint(sm[BUF_F + rA * STRQ + k * 8 + 4 + cA]);
        qa[k][3] = __float_as_uint(sm[BUF_F + (rA + 8) * STRQ + k * 8 + 4 + cA]);
    }

    // ---- Fill buf0 (chunk 0): LDG -> tf32r -> STS ----
    {
        const int kbase = q0 - 128;
        #pragma unroll
        for (int i = 0; i < 4; i++) {
            int row = g_row + i * 16;
            int gk  = kbase + row;
            float4 kv = make_float4(0.f, 0.f, 0.f, 0.f), vv = kv;
            if ((unsigned)gk < (unsigned)T_FIX) {
                kv = Kg[(size_t)gk * 16 + g_c4];
                vv = Vg[(size_t)gk * 16 + g_c4];
            }
            kv.x = tf32r(kv.x); kv.y = tf32r(kv.y);
            kv.z = tf32r(kv.z); kv.w = tf32r(kv.w);
            vv.x = tf32r(vv.x); vv.y = tf32r(vv.y);
            vv.z = tf32r(vv.z); vv.w = tf32r(vv.w);
            *(float4*)&sm[row * STRK + g_c4 * 4] = kv;
            *(float4*)&sm[KBUF_F + row * STRV + g_c4 * 4] = vv;
        }
    }
    __syncthreads();

    float o[8][4];
    #pragma unroll
    for (int n = 0; n < 8; n++)
        #pragma unroll
        for (int j = 0; j < 4; j++) o[n][j] = 0.f;
    float l0 = 0.f, l1 = 0.f;

    const int srcA = (lane & ~3) | (cA >> 1);   // shuffle sources for C->A transpose
    const int srcB = srcA + 2;
    const bool odd = (cA & 1) != 0;

    for (int c = 0; c < 6; c++) {
        const int kbase = q0 - 128 + c * 64;
        const int kvf   = (c & 1) * BUF_F;
        const int vvf   = kvf + KBUF_F;

        // ---- prefetch next chunk into registers (overlaps compute below) ----
        float4 pk[4], pv[4];
        if (c < 5) {
            const int kbn = kbase + 64;
            #pragma unroll
            for (int i = 0; i < 4; i++) {
                int row = g_row + i * 16;
                int gk  = kbn + row;
                float4 z = make_float4(0.f, 0.f, 0.f, 0.f);
                pk[i] = z; pv[i] = z;
                if ((unsigned)gk < (unsigned)T_FIX) {
                    pk[i] = Kg[(size_t)gk * 16 + g_c4];
                    pv[i] = Vg[(size_t)gk * 16 + g_c4];
                }
            }
        }

        // ---- fused per-tile: QK -> mask/exp2 -> shuffle transpose -> PV ----
        #pragma unroll
        for (int n = 0; n < 8; n++) {
            const int gt = c * 8 + n;
            if (gt < wlo || gt > whi) continue;     // warp-uniform skip

            float s[4]  = {0.f, 0.f, 0.f, 0.f};
            float s2[4] = {0.f, 0.f, 0.f, 0.f};
            const float* kr = &sm[kvf + (n * 8 + (lane >> 2)) * STRK + cA];
            #pragma unroll
            for (int k = 0; k < 8; k += 2) {
                uint32_t b0 = __float_as_uint(kr[k * 8]);
                uint32_t b1 = __float_as_uint(kr[k * 8 + 4]);
                mma8(s, qa[k], b0, b1);
                uint32_t b2 = __float_as_uint(kr[k * 8 + 8]);
                uint32_t b3 = __float_as_uint(kr[k * 8 + 12]);
                mma8(s2, qa[k + 1], b2, b3);
            }
            #pragma unroll
            for (int j = 0; j < 4; j++) s[j] += s2[j];

            int cc  = c * 64 + n * 8 + 2 * cA;      // local key col of c0
            int gk0 = kbase + n * 8 + 2 * cA;       // global key of c0
            bool in0 = ((unsigned)gk0       < (unsigned)T_FIX);
            bool in1 = ((unsigned)(gk0 + 1) < (unsigned)T_FIX);
            bool v00 = ((unsigned)(cc     - rA)       < 256u) && in0;
            bool v01 = ((unsigned)(cc + 1 - rA)       < 256u) && in1;
            bool v10 = ((unsigned)(cc     - (rA + 8)) < 256u) && in0;
            bool v11 = ((unsigned)(cc + 1 - (rA + 8)) < 256u) && in1;
            float p00 = v00 ? ex2(s[0]) : 0.f;
            float p01 = v01 ? ex2(s[1]) : 0.f;
            float p10 = v10 ? ex2(s[2]) : 0.f;
            float p11 = v11 ? ex2(s[3]) : 0.f;
            l0 += p00 + p01;
            l1 += p10 + p11;

            // C-frag (rows rA/rA+8, cols 2cA,2cA+1) -> A-frag via quad shuffles
            uint32_t c0 = __float_as_uint(tf32r(p00));
            uint32_t c1 = __float_as_uint(tf32r(p01));
            uint32_t c2 = __float_as_uint(tf32r(p10));
            uint32_t c3 = __float_as_uint(tf32r(p11));
            uint32_t t0 = __shfl_sync(0xffffffffu, c0, srcA);
            uint32_t t1 = __shfl_sync(0xffffffffu, c1, srcA);
            uint32_t u0 = __shfl_sync(0xffffffffu, c0, srcB);
            uint32_t u1 = __shfl_sync(0xffffffffu, c1, srcB);
            uint32_t t2 = __shfl_sync(0xffffffffu, c2, srcA);
            uint32_t t3 = __shfl_sync(0xffffffffu, c3, srcA);
            uint32_t u2 = __shfl_sync(0xffffffffu, c2, srcB);
            uint32_t u3 = __shfl_sync(0xffffffffu, c3, srcB);
            uint32_t a[4];
            a[0] = odd ? t1 : t0;   // P[rA][n*8+cA]
            a[1] = odd ? t3 : t2;   // P[rA+8][n*8+cA]
            a[2] = odd ? u1 : u0;   // P[rA][n*8+cA+4]
            a[3] = odd ? u3 : u2;   // P[rA+8][n*8+cA+4]

            // PV for this tile's 8 keys
            const float* vr0 = &sm[vvf + (n * 8 + cA) * STRV + (lane >> 2)];
            const float* vr1 = &sm[vvf + (n * 8 + 4 + cA) * STRV + (lane >> 2)];
            #pragma unroll
            for (int nd = 0; nd < 8; nd++) {
                uint32_t b0 = __float_as_uint(vr0[nd * 8]);
                uint32_t b1 = __float_as_uint(vr1[nd * 8]);
                mma8(o[nd], a, b0, b1);
            }
        }

        // ---- store prefetched chunk into the other buffer ----
        if (c < 5) {
            const int nkvf = ((c + 1) & 1) * BUF_F;
            const int nvvf = nkvf + KBUF_F;
            #pragma unroll
            for (int i = 0; i < 4; i++) {
                int row = g_row + i * 16;
                float4 kv = pk[i], vv = pv[i];
                kv.x = tf32r(kv.x); kv.y = tf32r(kv.y);
                kv.z = tf32r(kv.z); kv.w = tf32r(kv.w);
                vv.x = tf32r(vv.x); vv.y = tf32r(vv.y);
                vv.z = tf32r(vv.z); vv.w = tf32r(vv.w);
                *(float4*)&sm[nkvf + row * STRK + g_c4 * 4] = kv;
                *(float4*)&sm[nvvf + row * STRV + g_c4 * 4] = vv;
            }
        }
        __syncthreads();
    }

    // ---- normalize rows and store ----
    l0 += __shfl_xor_sync(0xffffffffu, l0, 1);
    l0 += __shfl_xor_sync(0xffffffffu, l0, 2);
    l1 += __shfl_xor_sync(0xffffffffu, l1, 1);
    l1 += __shfl_xor_sync(0xffffffffu, l1, 2);
    const float inv0 = __frcp_rn(l0);
    const float inv1 = __frcp_rn(l1);

    float* orow0 = Ob + (size_t)(q0 + rA) * 64;
    float* orow1 = Ob + (size_t)(q0 + rA + 8) * 64;
    #pragma unroll
    for (int nd = 0; nd < 8; nd++) {
        float2 u0 = make_float2(o[nd][0] * inv0, o[nd][1] * inv0);
        float2 u1 = make_float2(o[nd][2] * inv1, o[nd][3] * inv1);
        *(float2*)(orow0 + nd * 8 + 2 * cA) = u0;
        *(float2*)(orow1 + nd * 8 + 2 * cA) = u1;
    }
}

extern "C" void kernel_launch(void* const* d_in, const int* in_sizes, int n_in,
                              void* d_out, int out_size) {
    const float* Q = (const float*)d_in[0];
    const float* K = (const float*)d_in[1];
    const float* V = (const float*)d_in[2];
    float*       O = (float*)d_out;

    const int BH = in_sizes[0] / (T_FIX * 64);      // 24
    static bool attr_set = false;
    if (!attr_set) {
        cudaFuncSetAttribute(swa_mma_kernel,
                             cudaFuncAttributeMaxDynamicSharedMemorySize, SM_BYTES);
        attr_set = true;
    }
    dim3 grid(BH * (T_FIX / MQ));                   // 768
    swa_mma_kernel<<<grid, 256, SM_BYTES>>>(Q, K, V, O);
}

// round 8
// speedup vs baseline: 2.2706x; 2.0809x over previous
#include <cuda_runtime.h>
#include <cuda_fp16.h>
#include <cstdint>

// Sliding-window attention B=2 H=12 T=4096 D=64 fp32, window [q-128, q+127].
// fp16 m16n8k16 mma.sync (same 10-bit mantissa as tf32, 2x rate, half the
// smem traffic). ldmatrix for K/V fragments; P goes c-frag -> a-frag in
// registers (no smem round trip, no shuffles). Per-warp band skipping at
// 16-key pair granularity. CTA = 128 queries (8 warps x m16), 6 chunks of 64.

constexpr int T_FIX = 4096;
constexpr int MQ    = 128;
constexpr int STR   = 36;     // row stride in u32 (half2) units; 4r+c banks -> conflict-free

__device__ __forceinline__ uint32_t smem_u32(const void* p) {
    uint32_t a;
    asm("{ .reg .u64 t; cvta.to.shared.u64 t, %1; cvt.u32.u64 %0, t; }" : "=r"(a) : "l"(p));
    return a;
}
__device__ __forceinline__ float ex2(float x) {
    float y; asm("ex2.approx.ftz.f32 %0, %1;" : "=f"(y) : "f"(x)); return y;
}
__device__ __forceinline__ uint32_t packh2(float lo, float hi) {
    __half2 h = __floats2half2_rn(lo, hi);
    return *(uint32_t*)&h;
}
__device__ __forceinline__ void mma16(float* c, const uint32_t* a,
                                      uint32_t b0, uint32_t b1) {
    asm volatile(
        "mma.sync.aligned.m16n8k16.row.col.f32.f16.f16.f32 "
        "{%0,%1,%2,%3}, {%4,%5,%6,%7}, {%8,%9}, {%0,%1,%2,%3};"
        : "+f"(c[0]), "+f"(c[1]), "+f"(c[2]), "+f"(c[3])
        : "r"(a[0]), "r"(a[1]), "r"(a[2]), "r"(a[3]), "r"(b0), "r"(b1));
}
#define LDSM4(r0,r1,r2,r3,addr) \
    asm volatile("ldmatrix.sync.aligned.m8n8.x4.shared.b16 {%0,%1,%2,%3}, [%4];" \
        : "=r"(r0),"=r"(r1),"=r"(r2),"=r"(r3) : "r"(addr))
#define LDSM4T(r0,r1,r2,r3,addr) \
    asm volatile("ldmatrix.sync.aligned.m8n8.x4.trans.shared.b16 {%0,%1,%2,%3}, [%4];" \
        : "=r"(r0),"=r"(r1),"=r"(r2),"=r"(r3) : "r"(addr))

__global__ __launch_bounds__(256, 2)
void swa_f16_kernel(const float* __restrict__ Q, const float* __restrict__ K,
                    const float* __restrict__ V, float* __restrict__ O)
{
    __shared__ __align__(16) uint32_t sQ[128 * STR];
    __shared__ __align__(16) uint32_t sK[64 * STR];
    __shared__ __align__(16) uint32_t sV[64 * STR];

    const int tid  = threadIdx.x;
    const int lane = tid & 31;
    const int w    = tid >> 5;

    const int ntiles = T_FIX / MQ;                  // 32
    const int bh = blockIdx.x / ntiles;
    const int q0 = (blockIdx.x % ntiles) * MQ;
    const size_t base = (size_t)bh * T_FIX * 64;
    const float4* Qg = (const float4*)(Q + base);
    const float4* Kg = (const float4*)(K + base);
    const float4* Vg = (const float4*)(V + base);
    float*        Ob = O + base;

    const float SC = 1.4426950408889634f * 0.125f;  // log2(e)/sqrt(64)

    // ---- Stage Q (scaled, f16) ----
    #pragma unroll
    for (int i = 0; i < 8; i++) {
        int idx = tid + i * 256;
        int row = idx >> 4, c4 = idx & 15;
        float4 v = Qg[(size_t)(q0 + row) * 16 + c4];
        sQ[row * STR + c4 * 2]     = packh2(v.x * SC, v.y * SC);
        sQ[row * STR + c4 * 2 + 1] = packh2(v.z * SC, v.w * SC);
    }
    __syncthreads();

    // ---- Q a-fragments (m16n8k16): qa[s] covers dims 16s..16s+15 ----
    const int rA = w * 16 + (lane >> 2);
    const int cA = lane & 3;
    uint32_t qa[4][4];
    #pragma unroll
    for (int s = 0; s < 4; s++) {
        qa[s][0] = sQ[rA * STR + s * 8 + cA];
        qa[s][1] = sQ[(rA + 8) * STR + s * 8 + cA];
        qa[s][2] = sQ[rA * STR + s * 8 + 4 + cA];
        qa[s][3] = sQ[(rA + 8) * STR + s * 8 + 4 + cA];
    }

    // ---- ldmatrix per-lane base addresses (bytes) ----
    const int lr  = lane & 7;
    const int hib = (lane >> 3) & 1;
    const int sec = lane >> 4;
    // QK (non-trans): matrices {tile n0 dims-lo, n0 dims-hi, n1 dims-lo, n1 dims-hi}
    const uint32_t qk_base = smem_u32(sK) + ((sec * 8 + lr) * STR + hib * 4) * 4;
    // PV (trans): matrices {keys-lo nd, keys-hi nd, keys-lo nd+1, keys-hi nd+1}
    const uint32_t pv_base = smem_u32(sV) + ((hib * 8 + lr) * STR + sec * 4) * 4;

    float o[8][4];
    #pragma unroll
    for (int n = 0; n < 8; n++)
        #pragma unroll
        for (int j = 0; j < 4; j++) o[n][j] = 0.f;
    float l0 = 0.f, l1 = 0.f;

    for (int c = 0; c < 6; c++) {
        const int kbase = q0 - 128 + c * 64;

        __syncthreads();
        // ---- Fill K and V (f16, zero OOB rows) ----
        #pragma unroll
        for (int i = 0; i < 4; i++) {
            int idx = tid + i * 256;
            int key = idx >> 4, c4 = idx & 15;
            int gk  = kbase + key;
            float4 kv = make_float4(0.f, 0.f, 0.f, 0.f), vv = kv;
            if ((unsigned)gk < (unsigned)T_FIX) {
                kv = Kg[(size_t)gk * 16 + c4];
                vv = Vg[(size_t)gk * 16 + c4];
            }
            sK[key * STR + c4 * 2]     = packh2(kv.x, kv.y);
            sK[key * STR + c4 * 2 + 1] = packh2(kv.z, kv.w);
            sV[key * STR + c4 * 2]     = packh2(vv.x, vv.y);
            sV[key * STR + c4 * 2 + 1] = packh2(vv.z, vv.w);
        }
        __syncthreads();

        // ---- 4 pairs of 16 keys each ----
        #pragma unroll
        for (int st = 0; st < 4; st++) {
            const int gp = c * 4 + st;
            if (gp < w || gp > w + 16) continue;    // warp-uniform band skip

            // -- QK: two 8-key tiles, 4 k-steps of 16 dims --
            float sA[4] = {0.f, 0.f, 0.f, 0.f};
            float sB[4] = {0.f, 0.f, 0.f, 0.f};
            const uint32_t qk_p = qk_base + (st * 16 * STR) * 4;
            #pragma unroll
            for (int s = 0; s < 4; s++) {
                uint32_t r0, r1, r2, r3;
                LDSM4(r0, r1, r2, r3, qk_p + s * 32);
                mma16(sA, qa[s], r0, r1);
                mma16(sB, qa[s], r2, r3);
            }

            // -- mask + exp2 --
            const int cc  = c * 64 + st * 16 + 2 * cA;  // local col of sA c0
            const int gk0 = kbase + st * 16 + 2 * cA;
            bool iA0 = (unsigned)gk0       < (unsigned)T_FIX;
            bool iA1 = (unsigned)(gk0 + 1) < (unsigned)T_FIX;
            bool iB0 = (unsigned)(gk0 + 8) < (unsigned)T_FIX;
            bool iB1 = (unsigned)(gk0 + 9) < (unsigned)T_FIX;
            float pA00 = (((unsigned)(cc     - rA)      < 256u) && iA0) ? ex2(sA[0]) : 0.f;
            float pA01 = (((unsigned)(cc + 1 - rA)      < 256u) && iA1) ? ex2(sA[1]) : 0.f;
            float pA10 = (((unsigned)(cc     - rA - 8)  < 256u) && iA0) ? ex2(sA[2]) : 0.f;
            float pA11 = (((unsigned)(cc + 1 - rA - 8)  < 256u) && iA1) ? ex2(sA[3]) : 0.f;
            float pB00 = (((unsigned)(cc + 8 - rA)      < 256u) && iB0) ? ex2(sB[0]) : 0.f;
            float pB01 = (((unsigned)(cc + 9 - rA)      < 256u) && iB1) ? ex2(sB[1]) : 0.f;
            float pB10 = (((unsigned)(cc + 8 - rA - 8)  < 256u) && iB0) ? ex2(sB[2]) : 0.f;
            float pB11 = (((unsigned)(cc + 9 - rA - 8)  < 256u) && iB1) ? ex2(sB[3]) : 0.f;
            l0 += (pA00 + pA01) + (pB00 + pB01);
            l1 += (pA10 + pA11) + (pB10 + pB11);

            // -- c-frag -> PV a-frag, in registers --
            uint32_t pa[4];
            pa[0] = packh2(pA00, pA01);   // rows rA,   keys 16st+2cA,+1
            pa[1] = packh2(pA10, pA11);   // rows rA+8
            pa[2] = packh2(pB00, pB01);   // rows rA,   keys +8
            pa[3] = packh2(pB10, pB11);   // rows rA+8, keys +8

            // -- PV: one k16-step over these 16 keys, 8 dim-tiles --
            const uint32_t pv_p = pv_base + (st * 16 * STR) * 4;
            #pragma unroll
            for (int ndp = 0; ndp < 4; ndp++) {
                uint32_t v0, v1, v2, v3;
                LDSM4T(v0, v1, v2, v3, pv_p + ndp * 32);
                mma16(o[2 * ndp],     pa, v0, v1);
                mma16(o[2 * ndp + 1], pa, v2, v3);
            }
        }
    }

    // ---- normalize rows and store ----
    l0 += __shfl_xor_sync(0xffffffffu, l0, 1);
    l0 += __shfl_xor_sync(0xffffffffu, l0, 2);
    l1 += __shfl_xor_sync(0xffffffffu, l1, 1);
    l1 += __shfl_xor_sync(0xffffffffu, l1, 2);
    const float inv0 = __frcp_rn(l0);
    const float inv1 = __frcp_rn(l1);

    float* orow0 = Ob + (size_t)(q0 + rA) * 64;
    float* orow1 = Ob + (size_t)(q0 + rA + 8) * 64;
    #pragma unroll
    for (int nd = 0; nd < 8; nd++) {
        float2 u0 = make_float2(o[nd][0] * inv0, o[nd][1] * inv0);
        float2 u1 = make_float2(o[nd][2] * inv1, o[nd][3] * inv1);
        *(float2*)(orow0 + nd * 8 + 2 * cA) = u0;
        *(float2*)(orow1 + nd * 8 + 2 * cA) = u1;
    }
}

extern "C" void kernel_launch(void* const* d_in, const int* in_sizes, int n_in,
                              void* d_out, int out_size) {
    const float* Q = (const float*)d_in[0];
    const float* K = (const float*)d_in[1];
    const float* V = (const float*)d_in[2];
    float*       O = (float*)d_out;

    const int BH = in_sizes[0] / (T_FIX * 64);      // 24
    dim3 grid(BH * (T_FIX / MQ));                   // 768
    swa_f16_kernel<<<grid, 256>>>(Q, K, V, O);
}